// round 6
// baseline (speedup 1.0000x reference)
#include <cuda_runtime.h>
#include <cuda_fp16.h>
#include <cstdint>

// Problem constants (fixed instance)
#define DM   128      // model dim
#define HH   8        // heads
#define DHD  16       // head dim
#define MV   3        // views
#define MAXN 100000
#define MAXE 1600000

typedef unsigned long long ull;

// ---------------- scratch (static __device__ — no allocations) ----------------
__device__ float  g_q[(size_t)MAXN * DM];
__device__ float  g_k[(size_t)MAXN * DM];
__device__ __half g_vh[(size_t)MAXN * DM];   // V stored fp16 (read-only gather)
__device__ float  g_mix[(size_t)MAXE * HH];  // per-(csr-pos, head) mixture weight
__device__ float  g_inv[(size_t)MAXN * HH];  // per (node, head) 1/sum
__device__ int    g_count[MAXN];
__device__ int    g_rowptr[MAXN + 1];
__device__ int    g_rowfill[MAXN];
__device__ int    g_bsum[128];
__device__ int    g_boff[128];
__device__ int2   g_elist[MAXE];             // (edge_id, src)

// ---------------- packed f32x2 helpers ----------------
__device__ __forceinline__ ull fma2(ull a, ull b, ull c) {
    ull d;
    asm("fma.rn.f32x2 %0, %1, %2, %3;" : "=l"(d) : "l"(a), "l"(b), "l"(c));
    return d;
}
__device__ __forceinline__ ull bcast2(float x) {
    ull d;
    asm("mov.b64 %0, {%1, %1};" : "=l"(d) : "r"(__float_as_uint(x)));
    return d;
}

// ---------------- CSR build ----------------
__global__ void zero_count_kernel(int n) {
    int i = blockIdx.x * blockDim.x + threadIdx.x;
    if (i < n) g_count[i] = 0;
}

__global__ void hist_kernel(const int* __restrict__ dst, int e) {
    for (int i = blockIdx.x * blockDim.x + threadIdx.x; i < e; i += gridDim.x * blockDim.x)
        atomicAdd(&g_count[__ldcs(dst + i)], 1);
}

// per-1024-chunk exclusive scan; block totals to g_bsum
__global__ __launch_bounds__(1024) void blockscan_kernel(int n) {
    __shared__ int s_wsum[32];
    const int tid = threadIdx.x;
    const int lane = tid & 31, wid = tid >> 5;
    const int i = blockIdx.x * 1024 + tid;
    int v = (i < n) ? g_count[i] : 0;
    int x = v;
#pragma unroll
    for (int o = 1; o < 32; o <<= 1) {
        int t = __shfl_up_sync(0xffffffffu, x, o);
        if (lane >= o) x += t;
    }
    if (lane == 31) s_wsum[wid] = x;
    __syncthreads();
    if (wid == 0) {
        int ws = s_wsum[lane];
#pragma unroll
        for (int o = 1; o < 32; o <<= 1) {
            int t = __shfl_up_sync(0xffffffffu, ws, o);
            if (lane >= o) ws += t;
        }
        s_wsum[lane] = ws;
    }
    __syncthreads();
    int excl = (wid ? s_wsum[wid - 1] : 0) + (x - v);
    if (i < n) g_rowptr[i] = excl;
    if (tid == 0) g_bsum[blockIdx.x] = s_wsum[31];
}

// scan the (<=128) block totals on one warp; writes rowptr[n]
__global__ void bsumscan_kernel(int nb, int n) {
    const int lane = threadIdx.x;
    int carry = 0;
    for (int base = 0; base < nb; base += 32) {
        int idx = base + lane;
        int v = (idx < nb) ? g_bsum[idx] : 0;
        int x = v;
#pragma unroll
        for (int o = 1; o < 32; o <<= 1) {
            int t = __shfl_up_sync(0xffffffffu, x, o);
            if (lane >= o) x += t;
        }
        if (idx < nb) g_boff[idx] = carry + (x - v);
        carry += __shfl_sync(0xffffffffu, x, 31);
    }
    if (lane == 0) g_rowptr[n] = carry;
}

__global__ void addoff_kernel(int n) {
    int i = blockIdx.x * blockDim.x + threadIdx.x;
    if (i < n) {
        int r = g_rowptr[i] + g_boff[i >> 10];
        g_rowptr[i] = r;
        g_rowfill[i] = r;
    }
}

// scatter + per-edge mixture precompute.
// Reads dst/src/view_w SEQUENTIALLY (edge order), gathers pi[dst] (L2-resident 9.6MB),
// writes elist + 8 per-head mix values at the CSR position.
__global__ void scatter_kernel(const int* __restrict__ src, const int* __restrict__ dst,
                               const float* __restrict__ pi, const float* __restrict__ view_w,
                               int e)
{
    for (int i = blockIdx.x * blockDim.x + threadIdx.x; i < e; i += gridDim.x * blockDim.x) {
        const int d = __ldcs(dst + i);
        const int pos = atomicAdd(&g_rowfill[d], 1);
        g_elist[pos] = make_int2(i, __ldcs(src + i));
        const float w0 = __ldcs(view_w + (size_t)i * MV + 0);
        const float w1 = __ldcs(view_w + (size_t)i * MV + 1);
        const float w2 = __ldcs(view_w + (size_t)i * MV + 2);
        const float* pip = pi + (size_t)d * (HH * MV);
        float* mx = g_mix + (size_t)pos * HH;
#pragma unroll
        for (int h = 0; h < HH; h++)
            mx[h] = pip[h * MV + 0] * w0 + pip[h * MV + 1] * w1 + pip[h * MV + 2] * w2;
    }
}

// ---------------- fused QKV projection (fp32 math, packed f32x2 FMA) ----------------
__global__ __launch_bounds__(256) void qkv_kernel(
    const float* __restrict__ x,
    const float* __restrict__ Wq, const float* __restrict__ bqv,
    const float* __restrict__ Wk, const float* __restrict__ bkv,
    const float* __restrict__ Wv, const float* __restrict__ bvv,
    int n)
{
    __shared__ float sx[32][DM];  // 16KB
    const int row0 = blockIdx.x * 32;

    for (int t = threadIdx.x; t < 32 * 32; t += 256) {
        int r = t >> 5, c4 = t & 31;
        int row = row0 + r;
        float4 xv = make_float4(0.f, 0.f, 0.f, 0.f);
        if (row < n) xv = __ldcs((const float4*)(x + (size_t)row * DM + c4 * 4));
        *(float4*)(&sx[r][c4 * 4]) = xv;
    }
    __syncthreads();

    const int cp = threadIdx.x & 63;
    const int rg = threadIdx.x >> 6;
    const int c  = cp * 2;

    const ull* wq8 = reinterpret_cast<const ull*>(Wq) + cp;
    const ull* wk8 = reinterpret_cast<const ull*>(Wk) + cp;
    const ull* wv8 = reinterpret_cast<const ull*>(Wv) + cp;

    ull bq2 = reinterpret_cast<const ull*>(bqv)[cp];
    ull bk2 = reinterpret_cast<const ull*>(bkv)[cp];
    ull bv2 = reinterpret_cast<const ull*>(bvv)[cp];

    ull aq[8], ak[8], av[8];
#pragma unroll
    for (int r = 0; r < 8; r++) { aq[r] = bq2; ak[r] = bk2; av[r] = bv2; }

#pragma unroll 8
    for (int d = 0; d < DM; d++) {
        ull wq = wq8[(size_t)d * 64];
        ull wk = wk8[(size_t)d * 64];
        ull wv = wv8[(size_t)d * 64];
#pragma unroll
        for (int r = 0; r < 8; r++) {
            ull x2 = bcast2(sx[rg * 8 + r][d]);
            aq[r] = fma2(x2, wq, aq[r]);
            ak[r] = fma2(x2, wk, ak[r]);
            av[r] = fma2(x2, wv, av[r]);
        }
    }

#pragma unroll
    for (int r = 0; r < 8; r++) {
        int row = row0 + rg * 8 + r;
        if (row < n) {
            *(ull*)(g_q + (size_t)row * DM + c) = aq[r];
            *(ull*)(g_k + (size_t)row * DM + c) = ak[r];
            float2 vf;
            vf.x = __uint_as_float((unsigned)(av[r] & 0xffffffffu));
            vf.y = __uint_as_float((unsigned)(av[r] >> 32));
            *(__half2*)(g_vh + (size_t)row * DM + c) = __float22half2_rn(vf);
        }
    }
}

// ---------------- single-pass node kernel ----------------
// One warp per node. Lane l owns features [4l,4l+4), head h = l>>2.
// Streams: elist, mix, attn-out, q, states-out use evict-first (.cs) so L2 stays
// reserved for the hot k (fp32) + v (fp16) gather arrays.
__global__ __launch_bounds__(256) void node_kernel(
    float* __restrict__ out_states,   // [N, 128]
    float* __restrict__ out_attn,     // [E, 8] (unnormalized here)
    int n)
{
    const int nd = blockIdx.x * (blockDim.x >> 5) + (threadIdx.x >> 5);
    if (nd >= n) return;
    const int lane = threadIdx.x & 31;
    const unsigned FULL = 0xffffffffu;
    const int h = lane >> 2;

    const int beg = g_rowptr[nd];
    const int end = g_rowptr[nd + 1];

    const float4 qv = __ldcs((const float4*)(g_q + (size_t)nd * DM + lane * 4));

    float ssum = 0.f;
    float4 acc = make_float4(0.f, 0.f, 0.f, 0.f);

    int i = beg;
    for (; i + 1 < end; i += 2) {
        const int2 eA = __ldcs(&g_elist[i]);
        const int2 eB = __ldcs(&g_elist[i + 1]);
        const float mixA = __ldcs(&g_mix[(size_t)i * HH + h]);
        const float mixB = __ldcs(&g_mix[(size_t)(i + 1) * HH + h]);

        // 4 independent gathers in flight
        const float4 kA = *(const float4*)(g_k + (size_t)eA.y * DM + lane * 4);
        const float4 kB = *(const float4*)(g_k + (size_t)eB.y * DM + lane * 4);
        const uint2  vA = *(const uint2*)(g_vh + (size_t)eA.y * DM + lane * 4);
        const uint2  vB = *(const uint2*)(g_vh + (size_t)eB.y * DM + lane * 4);

        float pA = qv.x * kA.x + qv.y * kA.y + qv.z * kA.z + qv.w * kA.w;
        float pB = qv.x * kB.x + qv.y * kB.y + qv.z * kB.z + qv.w * kB.w;
        pA += __shfl_xor_sync(FULL, pA, 1);
        pB += __shfl_xor_sync(FULL, pB, 1);
        pA += __shfl_xor_sync(FULL, pA, 2);
        pB += __shfl_xor_sync(FULL, pB, 2);

        const float wA = (mixA > 0.f) ? __expf(pA * 0.25f) * fmaxf(mixA, 1e-8f) : 0.f;
        const float wB = (mixB > 0.f) ? __expf(pB * 0.25f) * fmaxf(mixB, 1e-8f) : 0.f;
        ssum += wA + wB;

        const float wlA = __shfl_sync(FULL, wA, (lane & 7) * 4);
        const float wlB = __shfl_sync(FULL, wB, (lane & 7) * 4);
        if (lane < 8) {
            __stcs(&out_attn[(size_t)eA.x * HH + lane], wlA);
            __stcs(&out_attn[(size_t)eB.x * HH + lane], wlB);
        }

        const float2 a01 = __half22float2(*(const __half2*)&vA.x);
        const float2 a23 = __half22float2(*(const __half2*)&vA.y);
        const float2 b01 = __half22float2(*(const __half2*)&vB.x);
        const float2 b23 = __half22float2(*(const __half2*)&vB.y);
        acc.x += a01.x * wA + b01.x * wB;
        acc.y += a01.y * wA + b01.y * wB;
        acc.z += a23.x * wA + b23.x * wB;
        acc.w += a23.y * wA + b23.y * wB;
    }
    if (i < end) {
        const int2 eA = __ldcs(&g_elist[i]);
        const float mixA = __ldcs(&g_mix[(size_t)i * HH + h]);
        const float4 kA = *(const float4*)(g_k + (size_t)eA.y * DM + lane * 4);
        const uint2  vA = *(const uint2*)(g_vh + (size_t)eA.y * DM + lane * 4);
        float pA = qv.x * kA.x + qv.y * kA.y + qv.z * kA.z + qv.w * kA.w;
        pA += __shfl_xor_sync(FULL, pA, 1);
        pA += __shfl_xor_sync(FULL, pA, 2);
        const float wA = (mixA > 0.f) ? __expf(pA * 0.25f) * fmaxf(mixA, 1e-8f) : 0.f;
        ssum += wA;
        const float wlA = __shfl_sync(FULL, wA, (lane & 7) * 4);
        if (lane < 8) __stcs(&out_attn[(size_t)eA.x * HH + lane], wlA);
        const float2 a01 = __half22float2(*(const __half2*)&vA.x);
        const float2 a23 = __half22float2(*(const __half2*)&vA.y);
        acc.x += a01.x * wA;
        acc.y += a01.y * wA;
        acc.z += a23.x * wA;
        acc.w += a23.y * wA;
    }

    const float inv = 1.f / fmaxf(ssum, 1e-8f);
    acc.x *= inv; acc.y *= inv; acc.z *= inv; acc.w *= inv;
    __stcs((float4*)(out_states + (size_t)nd * DM + lane * 4), acc);

    const float inv_h = __shfl_sync(FULL, inv, lane * 4);  // valid for lane<8
    if (lane < 8) g_inv[(size_t)nd * HH + lane] = inv_h;
}

// ---------------- edge-parallel attn normalization ----------------
__global__ __launch_bounds__(256) void normalize_kernel(
    const int* __restrict__ dst,
    float* __restrict__ out_attn,
    int e)
{
    const int i = blockIdx.x * blockDim.x + threadIdx.x;
    if (i >= e) return;
    const int d = __ldcs(dst + i);
    const float4 i0 = *(const float4*)(g_inv + (size_t)d * HH);
    const float4 i1 = *(const float4*)(g_inv + (size_t)d * HH + 4);
    float4 a0 = __ldcs((const float4*)(out_attn + (size_t)i * HH));
    float4 a1 = __ldcs((const float4*)(out_attn + (size_t)i * HH + 4));
    a0.x *= i0.x; a0.y *= i0.y; a0.z *= i0.z; a0.w *= i0.w;
    a1.x *= i1.x; a1.y *= i1.y; a1.z *= i1.z; a1.w *= i1.w;
    __stcs((float4*)(out_attn + (size_t)i * HH),     a0);
    __stcs((float4*)(out_attn + (size_t)i * HH + 4), a1);
}

// ---------------- launch ----------------
extern "C" void kernel_launch(void* const* d_in, const int* in_sizes, int n_in,
                              void* d_out, int out_size)
{
    const float* x   = (const float*)d_in[0];
    const float* pi  = (const float*)d_in[1];
    const float* vw  = (const float*)d_in[2];
    const float* Wq  = (const float*)d_in[3];
    const float* bq  = (const float*)d_in[4];
    const float* Wk  = (const float*)d_in[5];
    const float* bk  = (const float*)d_in[6];
    const float* Wv  = (const float*)d_in[7];
    const float* bv  = (const float*)d_in[8];
    const int*   src = (const int*)d_in[9];
    const int*   dst = (const int*)d_in[10];

    const int n = in_sizes[0] / DM;    // nodes
    const int e = in_sizes[10];        // edges

    float* out  = (float*)d_out;
    float* attn = out + (size_t)n * DM;

    int gb = (e + 255) / 256;
    if (gb > 4096) gb = 4096;

    const int nb = (n + 1023) / 1024;  // scan blocks (<=128)

    // QKV projection (independent of CSR build)
    qkv_kernel<<<(n + 31) / 32, 256>>>(x, Wq, bq, Wk, bk, Wv, bv, n);

    // CSR by dst (parallel 3-phase scan)
    zero_count_kernel<<<(n + 255) / 256, 256>>>(n);
    hist_kernel<<<gb, 256>>>(dst, e);
    blockscan_kernel<<<nb, 1024>>>(n);
    bsumscan_kernel<<<1, 32>>>(nb, n);
    addoff_kernel<<<(n + 255) / 256, 256>>>(n);
    scatter_kernel<<<gb, 256>>>(src, dst, pi, vw, e);

    // single-pass fused scores + softmax + aggregation
    node_kernel<<<(n + 7) / 8, 256>>>(out, attn, n);

    // edge-parallel attn normalization
    normalize_kernel<<<(e + 255) / 256, 256>>>(dst, attn, e);
}

// round 7
// speedup vs baseline: 1.3843x; 1.3843x over previous
#include <cuda_runtime.h>
#include <cuda_fp16.h>
#include <cstdint>

// Problem constants (fixed instance)
#define DM   128      // model dim
#define HH   8        // heads
#define DHD  16       // head dim
#define MV   3        // views
#define MAXN 100000
#define MAXE 1600000

typedef unsigned long long ull;

// ---------------- scratch (static __device__ — no allocations) ----------------
__device__ float  g_q[(size_t)MAXN * DM];
// interleaved K/V in fp16: per node, 32 slots of 16B: {k[4l..4l+1],k[4l+2..4l+3],v[4l..],v[..]}
__device__ uint4  g_kv[(size_t)MAXN * 32];
__device__ float  g_inv[(size_t)MAXN * HH];  // per (node, head) 1/sum
__device__ int    g_count[MAXN];
__device__ int    g_rowptr[MAXN + 1];
__device__ int    g_rowfill[MAXN];
__device__ int    g_bsum[128];
__device__ int    g_boff[128];
__device__ int2   g_elist[MAXE];             // (edge_id, src)

// ---------------- packed f32x2 helpers ----------------
__device__ __forceinline__ ull fma2(ull a, ull b, ull c) {
    ull d;
    asm("fma.rn.f32x2 %0, %1, %2, %3;" : "=l"(d) : "l"(a), "l"(b), "l"(c));
    return d;
}
__device__ __forceinline__ ull bcast2(float x) {
    ull d;
    asm("mov.b64 %0, {%1, %1};" : "=l"(d) : "r"(__float_as_uint(x)));
    return d;
}

// ---------------- CSR build ----------------
__global__ void zero_count_kernel(int n) {
    int i = blockIdx.x * blockDim.x + threadIdx.x;
    if (i < n) g_count[i] = 0;
}

__global__ void hist_kernel(const int* __restrict__ dst, int e) {
    for (int i = blockIdx.x * blockDim.x + threadIdx.x; i < e; i += gridDim.x * blockDim.x)
        atomicAdd(&g_count[dst[i]], 1);
}

// per-1024-chunk exclusive scan; block totals to g_bsum
__global__ __launch_bounds__(1024) void blockscan_kernel(int n) {
    __shared__ int s_wsum[32];
    const int tid = threadIdx.x;
    const int lane = tid & 31, wid = tid >> 5;
    const int i = blockIdx.x * 1024 + tid;
    int v = (i < n) ? g_count[i] : 0;
    int x = v;
#pragma unroll
    for (int o = 1; o < 32; o <<= 1) {
        int t = __shfl_up_sync(0xffffffffu, x, o);
        if (lane >= o) x += t;
    }
    if (lane == 31) s_wsum[wid] = x;
    __syncthreads();
    if (wid == 0) {
        int ws = s_wsum[lane];
#pragma unroll
        for (int o = 1; o < 32; o <<= 1) {
            int t = __shfl_up_sync(0xffffffffu, ws, o);
            if (lane >= o) ws += t;
        }
        s_wsum[lane] = ws;
    }
    __syncthreads();
    int excl = (wid ? s_wsum[wid - 1] : 0) + (x - v);
    if (i < n) g_rowptr[i] = excl;
    if (tid == 0) g_bsum[blockIdx.x] = s_wsum[31];
}

// scan the (<=128) block totals on one warp; writes rowptr[n]
__global__ void bsumscan_kernel(int nb, int n) {
    const int lane = threadIdx.x;
    int carry = 0;
    for (int base = 0; base < nb; base += 32) {
        int idx = base + lane;
        int v = (idx < nb) ? g_bsum[idx] : 0;
        int x = v;
#pragma unroll
        for (int o = 1; o < 32; o <<= 1) {
            int t = __shfl_up_sync(0xffffffffu, x, o);
            if (lane >= o) x += t;
        }
        if (idx < nb) g_boff[idx] = carry + (x - v);
        carry += __shfl_sync(0xffffffffu, x, 31);
    }
    if (lane == 0) g_rowptr[n] = carry;
}

__global__ void addoff_kernel(int n) {
    int i = blockIdx.x * blockDim.x + threadIdx.x;
    if (i < n) {
        int r = g_rowptr[i] + g_boff[i >> 10];
        g_rowptr[i] = r;
        g_rowfill[i] = r;
    }
}

__global__ void scatter_kernel(const int* __restrict__ src, const int* __restrict__ dst, int e) {
    for (int i = blockIdx.x * blockDim.x + threadIdx.x; i < e; i += gridDim.x * blockDim.x) {
        int d = dst[i];
        int pos = atomicAdd(&g_rowfill[d], 1);
        g_elist[pos] = make_int2(i, src[i]);
    }
}

// ---------------- fused QKV projection (fp32 math, packed f32x2 FMA) ----------------
// Q written fp32; K and V written fp16 into the interleaved g_kv layout.
__global__ __launch_bounds__(256) void qkv_kernel(
    const float* __restrict__ x,
    const float* __restrict__ Wq, const float* __restrict__ bqv,
    const float* __restrict__ Wk, const float* __restrict__ bkv,
    const float* __restrict__ Wv, const float* __restrict__ bvv,
    int n)
{
    __shared__ float sx[32][DM];  // 16KB
    const int row0 = blockIdx.x * 32;

    for (int t = threadIdx.x; t < 32 * 32; t += 256) {
        int r = t >> 5, c4 = t & 31;
        int row = row0 + r;
        float4 xv = make_float4(0.f, 0.f, 0.f, 0.f);
        if (row < n) xv = *(const float4*)(x + (size_t)row * DM + c4 * 4);
        *(float4*)(&sx[r][c4 * 4]) = xv;
    }
    __syncthreads();

    const int cp = threadIdx.x & 63;   // column pair 0..63 -> cols c=2cp, 2cp+1
    const int rg = threadIdx.x >> 6;
    const int c  = cp * 2;
    const int slot = c >> 2;           // 16B slot (4 cols) 0..31
    const int half = cp & 1;           // which half2 within the slot

    const ull* wq8 = reinterpret_cast<const ull*>(Wq) + cp;
    const ull* wk8 = reinterpret_cast<const ull*>(Wk) + cp;
    const ull* wv8 = reinterpret_cast<const ull*>(Wv) + cp;

    ull bq2 = reinterpret_cast<const ull*>(bqv)[cp];
    ull bk2 = reinterpret_cast<const ull*>(bkv)[cp];
    ull bv2 = reinterpret_cast<const ull*>(bvv)[cp];

    ull aq[8], ak[8], av[8];
#pragma unroll
    for (int r = 0; r < 8; r++) { aq[r] = bq2; ak[r] = bk2; av[r] = bv2; }

#pragma unroll 8
    for (int d = 0; d < DM; d++) {
        ull wq = wq8[(size_t)d * 64];
        ull wk = wk8[(size_t)d * 64];
        ull wv = wv8[(size_t)d * 64];
#pragma unroll
        for (int r = 0; r < 8; r++) {
            ull x2 = bcast2(sx[rg * 8 + r][d]);
            aq[r] = fma2(x2, wq, aq[r]);
            ak[r] = fma2(x2, wk, ak[r]);
            av[r] = fma2(x2, wv, av[r]);
        }
    }

#pragma unroll
    for (int r = 0; r < 8; r++) {
        int row = row0 + rg * 8 + r;
        if (row < n) {
            *(ull*)(g_q + (size_t)row * DM + c) = aq[r];
            float2 kf, vf;
            kf.x = __uint_as_float((unsigned)(ak[r] & 0xffffffffu));
            kf.y = __uint_as_float((unsigned)(ak[r] >> 32));
            vf.x = __uint_as_float((unsigned)(av[r] & 0xffffffffu));
            vf.y = __uint_as_float((unsigned)(av[r] >> 32));
            __half2* kvp = (__half2*)&g_kv[(size_t)row * 32 + slot];
            kvp[half]     = __float22half2_rn(kf);   // k half of slot
            kvp[2 + half] = __float22half2_rn(vf);   // v half of slot
        }
    }
}

// ---------------- single-pass node kernel: scores + weights + aggregation ----------------
// One warp per node. Lane l owns features [4l,4l+4), head h = l>>2.
// One uint4 gather per edge delivers both k (fp16) and v (fp16) for this lane.
__global__ __launch_bounds__(256) void node_kernel(
    const float* __restrict__ pi,
    const float* __restrict__ view_w,
    float* __restrict__ out_states,   // [N, 128]
    float* __restrict__ out_attn,     // [E, 8] (unnormalized here)
    int n)
{
    const int nd = blockIdx.x * (blockDim.x >> 5) + (threadIdx.x >> 5);
    if (nd >= n) return;
    const int lane = threadIdx.x & 31;
    const unsigned FULL = 0xffffffffu;

    const int beg = g_rowptr[nd];
    const int end = g_rowptr[nd + 1];

    const float4 qv = *(const float4*)(g_q + (size_t)nd * DM + lane * 4);
    const int h = lane >> 2;
    const float* pip = pi + (size_t)nd * (HH * MV) + h * MV;
    const float pi0 = pip[0], pi1 = pip[1], pi2 = pip[2];

    float ssum = 0.f;
    float4 acc = make_float4(0.f, 0.f, 0.f, 0.f);

    int i = beg;
    for (; i + 1 < end; i += 2) {
        const int2 eA = g_elist[i];
        const int2 eB = g_elist[i + 1];

        // two independent 16B gathers in flight
        const uint4 kvA = g_kv[(size_t)eA.y * 32 + lane];
        const uint4 kvB = g_kv[(size_t)eB.y * 32 + lane];

        const float* vwA = view_w + (size_t)eA.x * MV;
        const float* vwB = view_w + (size_t)eB.x * MV;
        const float mixA = pi0 * vwA[0] + pi1 * vwA[1] + pi2 * vwA[2];
        const float mixB = pi0 * vwB[0] + pi1 * vwB[1] + pi2 * vwB[2];

        const float2 kA01 = __half22float2(*(const __half2*)&kvA.x);
        const float2 kA23 = __half22float2(*(const __half2*)&kvA.y);
        const float2 kB01 = __half22float2(*(const __half2*)&kvB.x);
        const float2 kB23 = __half22float2(*(const __half2*)&kvB.y);

        float pA = qv.x * kA01.x + qv.y * kA01.y + qv.z * kA23.x + qv.w * kA23.y;
        float pB = qv.x * kB01.x + qv.y * kB01.y + qv.z * kB23.x + qv.w * kB23.y;
        pA += __shfl_xor_sync(FULL, pA, 1);
        pB += __shfl_xor_sync(FULL, pB, 1);
        pA += __shfl_xor_sync(FULL, pA, 2);
        pB += __shfl_xor_sync(FULL, pB, 2);

        const float wA = (mixA > 0.f) ? __expf(pA * 0.25f) * fmaxf(mixA, 1e-8f) : 0.f;
        const float wB = (mixB > 0.f) ? __expf(pB * 0.25f) * fmaxf(mixB, 1e-8f) : 0.f;
        ssum += wA + wB;

        const float wlA = __shfl_sync(FULL, wA, (lane & 7) * 4);
        const float wlB = __shfl_sync(FULL, wB, (lane & 7) * 4);
        if (lane < 8) {
            out_attn[(size_t)eA.x * HH + lane] = wlA;
            out_attn[(size_t)eB.x * HH + lane] = wlB;
        }

        const float2 vA01 = __half22float2(*(const __half2*)&kvA.z);
        const float2 vA23 = __half22float2(*(const __half2*)&kvA.w);
        const float2 vB01 = __half22float2(*(const __half2*)&kvB.z);
        const float2 vB23 = __half22float2(*(const __half2*)&kvB.w);
        acc.x += vA01.x * wA + vB01.x * wB;
        acc.y += vA01.y * wA + vB01.y * wB;
        acc.z += vA23.x * wA + vB23.x * wB;
        acc.w += vA23.y * wA + vB23.y * wB;
    }
    if (i < end) {
        const int2 eA = g_elist[i];
        const uint4 kvA = g_kv[(size_t)eA.y * 32 + lane];
        const float* vwA = view_w + (size_t)eA.x * MV;
        const float mixA = pi0 * vwA[0] + pi1 * vwA[1] + pi2 * vwA[2];
        const float2 kA01 = __half22float2(*(const __half2*)&kvA.x);
        const float2 kA23 = __half22float2(*(const __half2*)&kvA.y);
        float pA = qv.x * kA01.x + qv.y * kA01.y + qv.z * kA23.x + qv.w * kA23.y;
        pA += __shfl_xor_sync(FULL, pA, 1);
        pA += __shfl_xor_sync(FULL, pA, 2);
        const float wA = (mixA > 0.f) ? __expf(pA * 0.25f) * fmaxf(mixA, 1e-8f) : 0.f;
        ssum += wA;
        const float wlA = __shfl_sync(FULL, wA, (lane & 7) * 4);
        if (lane < 8) out_attn[(size_t)eA.x * HH + lane] = wlA;
        const float2 vA01 = __half22float2(*(const __half2*)&kvA.z);
        const float2 vA23 = __half22float2(*(const __half2*)&kvA.w);
        acc.x += vA01.x * wA;
        acc.y += vA01.y * wA;
        acc.z += vA23.x * wA;
        acc.w += vA23.y * wA;
    }

    const float inv = 1.f / fmaxf(ssum, 1e-8f);
    acc.x *= inv; acc.y *= inv; acc.z *= inv; acc.w *= inv;
    *(float4*)(out_states + (size_t)nd * DM + lane * 4) = acc;

    const float inv_h = __shfl_sync(FULL, inv, lane * 4);  // valid for lane<8
    if (lane < 8) g_inv[(size_t)nd * HH + lane] = inv_h;
}

// ---------------- edge-parallel attn normalization ----------------
__global__ __launch_bounds__(256) void normalize_kernel(
    const int* __restrict__ dst,
    float* __restrict__ out_attn,
    int e)
{
    const int i = blockIdx.x * blockDim.x + threadIdx.x;
    if (i >= e) return;
    const int d = dst[i];
    const float4 i0 = *(const float4*)(g_inv + (size_t)d * HH);
    const float4 i1 = *(const float4*)(g_inv + (size_t)d * HH + 4);
    float4 a0 = *(const float4*)(out_attn + (size_t)i * HH);
    float4 a1 = *(const float4*)(out_attn + (size_t)i * HH + 4);
    a0.x *= i0.x; a0.y *= i0.y; a0.z *= i0.z; a0.w *= i0.w;
    a1.x *= i1.x; a1.y *= i1.y; a1.z *= i1.z; a1.w *= i1.w;
    *(float4*)(out_attn + (size_t)i * HH)     = a0;
    *(float4*)(out_attn + (size_t)i * HH + 4) = a1;
}

// ---------------- launch ----------------
extern "C" void kernel_launch(void* const* d_in, const int* in_sizes, int n_in,
                              void* d_out, int out_size)
{
    const float* x   = (const float*)d_in[0];
    const float* pi  = (const float*)d_in[1];
    const float* vw  = (const float*)d_in[2];
    const float* Wq  = (const float*)d_in[3];
    const float* bq  = (const float*)d_in[4];
    const float* Wk  = (const float*)d_in[5];
    const float* bk  = (const float*)d_in[6];
    const float* Wv  = (const float*)d_in[7];
    const float* bv  = (const float*)d_in[8];
    const int*   src = (const int*)d_in[9];
    const int*   dst = (const int*)d_in[10];

    const int n = in_sizes[0] / DM;    // nodes
    const int e = in_sizes[10];        // edges

    float* out  = (float*)d_out;
    float* attn = out + (size_t)n * DM;

    int gb = (e + 255) / 256;
    if (gb > 4096) gb = 4096;

    const int nb = (n + 1023) / 1024;  // scan blocks (<=128)

    // QKV projection (independent of CSR build)
    qkv_kernel<<<(n + 31) / 32, 256>>>(x, Wq, bq, Wk, bk, Wv, bv, n);

    // CSR by dst (parallel 3-phase scan)
    zero_count_kernel<<<(n + 255) / 256, 256>>>(n);
    hist_kernel<<<gb, 256>>>(dst, e);
    blockscan_kernel<<<nb, 1024>>>(n);
    bsumscan_kernel<<<1, 32>>>(nb, n);
    addoff_kernel<<<(n + 255) / 256, 256>>>(n);
    scatter_kernel<<<gb, 256>>>(src, dst, e);

    // single-pass fused scores + softmax + aggregation
    node_kernel<<<(n + 7) / 8, 256>>>(pi, vw, out, attn, n);

    // edge-parallel attn normalization
    normalize_kernel<<<(e + 255) / 256, 256>>>(dst, attn, e);
}

// round 9
// speedup vs baseline: 1.6365x; 1.1822x over previous
#include <cuda_runtime.h>
#include <cuda_fp16.h>
#include <cuda_bf16.h>
#include <cstdint>

// Problem constants (fixed instance)
#define DM   128      // model dim
#define HH   8        // heads
#define MV   3        // views
#define MAXN 100000
#define MAXE 1600000

typedef unsigned long long ull;

// ---------------- scratch (static __device__ — no allocations) ----------------
__device__ float  g_q[(size_t)MAXN * DM];
// interleaved K/V in fp16: per node, 32 slots of 16B: {k01,k23,v01,v23}
__device__ uint4  g_kv[(size_t)MAXN * 32];
__device__ float  g_inv[(size_t)MAXN * HH];  // per (node, head) 1/sum
__device__ int    g_count[MAXN];
__device__ int    g_rowptr[MAXN + 1];
__device__ int    g_rowfill[MAXN];
__device__ int    g_bsum[128];
__device__ int    g_boff[128];
__device__ int2   g_elist[MAXE];             // (edge_id, src)
// W^T tiles, bf16: [mat(3)][split(2)][n(128)][k(128)]
__device__ __nv_bfloat16 g_wt[6 * 16384];

__device__ __forceinline__ uint32_t packbf2(float a, float b) {
    __nv_bfloat162 t = __floats2bfloat162_rn(a, b);
    return *(uint32_t*)&t;
}

// ---------------- W prep: transpose + bf16 hi/lo split ----------------
__global__ void prep_w_kernel(const float* __restrict__ Wq, const float* __restrict__ Wk,
                              const float* __restrict__ Wv) {
    const int idx = blockIdx.x * blockDim.x + threadIdx.x;
    if (idx >= 6 * 16384) return;
    const int ms  = idx >> 14;         // mat*2 + split
    const int rem = idx & 16383;
    const int nrow = rem >> 7;         // output column (B row) 0..127
    const int kcol = rem & 127;        // K 0..127
    const int m = ms >> 1, s = ms & 1;
    const float* W = (m == 0) ? Wq : ((m == 1) ? Wk : Wv);
    const float val = W[kcol * DM + nrow];   // B[k][n] = W[k][n]; stored as WT[n][k]
    __nv_bfloat16 h = __float2bfloat16(val);
    if (s == 1) h = __float2bfloat16(val - __bfloat162float(h));
    g_wt[(size_t)ms * 16384 + nrow * 128 + kcol] = h;
}

// ---------------- tensor-core QKV via baseline mma.sync (bf16 split, f32 accum) ----------------
// 256 threads = 8 warps in 2(M)x4(N); warp tile 64x32; CTA tile 128 rows x 128 cols per mat.
// SMEM: X hi/lo + W hi/lo, padded row stride 136 bf16 (conflict-free fragment LDS).
#define XPAD 136
#define QKV_SMEM_ELEMS (4 * 128 * XPAD)
#define QKV_SMEM_BYTES (QKV_SMEM_ELEMS * 2)

__device__ __forceinline__ void mma16816(float* c, const uint32_t* a, const uint32_t* b) {
    asm volatile(
        "mma.sync.aligned.m16n8k16.row.col.f32.bf16.bf16.f32 "
        "{%0,%1,%2,%3}, {%4,%5,%6,%7}, {%8,%9}, {%0,%1,%2,%3};"
        : "+f"(c[0]), "+f"(c[1]), "+f"(c[2]), "+f"(c[3])
        : "r"(a[0]), "r"(a[1]), "r"(a[2]), "r"(a[3]), "r"(b[0]), "r"(b[1]));
}

__global__ __launch_bounds__(256, 1) void qkv_mma_kernel(
    const float* __restrict__ x,
    const float* __restrict__ bq, const float* __restrict__ bk, const float* __restrict__ bv,
    int n)
{
    extern __shared__ __nv_bfloat16 sm[];
    __nv_bfloat16* sxh = sm;
    __nv_bfloat16* sxl = sm + 128 * XPAD;
    __nv_bfloat16* swh = sm + 2 * 128 * XPAD;
    __nv_bfloat16* swl = sm + 3 * 128 * XPAD;

    const int tid = threadIdx.x;
    const int wid = tid >> 5;
    const int lane = tid & 31;
    const int wm = wid & 1;            // M tile (0..1) of 64 rows
    const int wn = wid >> 1;           // N tile (0..3) of 32 cols
    const int g = lane >> 2;           // group 0..7
    const int tig = lane & 3;          // thread-in-group 0..3
    const int row0 = blockIdx.x * 128;

    // phase 1: load X tile, bf16 hi/lo split into SMEM
    for (int t = tid; t < 128 * 32; t += 256) {
        const int r = t >> 5, c4 = (t & 31) * 4;
        const int row = row0 + r;
        float4 f = make_float4(0.f, 0.f, 0.f, 0.f);
        if (row < n) f = *(const float4*)(x + (size_t)row * DM + c4);
        const __nv_bfloat16 h0 = __float2bfloat16(f.x), h1 = __float2bfloat16(f.y);
        const __nv_bfloat16 h2 = __float2bfloat16(f.z), h3 = __float2bfloat16(f.w);
        const int base = r * XPAD + c4;
        *(uint32_t*)(sxh + base)     = packbf2(__bfloat162float(h0), __bfloat162float(h1));
        *(uint32_t*)(sxh + base + 2) = packbf2(__bfloat162float(h2), __bfloat162float(h3));
        *(uint32_t*)(sxl + base)     = packbf2(f.x - __bfloat162float(h0), f.y - __bfloat162float(h1));
        *(uint32_t*)(sxl + base + 2) = packbf2(f.z - __bfloat162float(h2), f.w - __bfloat162float(h3));
    }

    for (int m = 0; m < 3; m++) {
        __syncthreads();   // X ready (m=0) / previous-mat MMA reads done (m>0)
        // phase 2: copy this mat's W^T hi/lo into padded SMEM (16B chunks)
        {
            const uint4* wh = (const uint4*)(g_wt + (size_t)(m * 2) * 16384);
            const uint4* wl = (const uint4*)(g_wt + (size_t)(m * 2 + 1) * 16384);
            for (int t = tid; t < 2048; t += 256) {
                const int r = t >> 4, seg = (t & 15) * 8;
                *(uint4*)(swh + r * XPAD + seg) = wh[t];
                *(uint4*)(swl + r * XPAD + seg) = wl[t];
            }
        }
        __syncthreads();

        float acc[4][4][4];
#pragma unroll
        for (int mf = 0; mf < 4; mf++)
#pragma unroll
            for (int nf = 0; nf < 4; nf++)
#pragma unroll
                for (int r = 0; r < 4; r++) acc[mf][nf][r] = 0.f;

#pragma unroll
        for (int s = 0; s < 3; s++) {  // (hi,hi), (hi,lo), (lo,hi)
            const __nv_bfloat16* A = (s == 2) ? sxl : sxh;
            const __nv_bfloat16* B = (s == 1) ? swl : swh;
#pragma unroll
            for (int ks = 0; ks < 8; ks++) {
                const int kb = ks * 16 + 2 * tig;
                uint32_t a[4][4], b[4][2];
#pragma unroll
                for (int mf = 0; mf < 4; mf++) {
                    const int ar = wm * 64 + mf * 16 + g;
                    a[mf][0] = *(const uint32_t*)(A + ar * XPAD + kb);
                    a[mf][1] = *(const uint32_t*)(A + (ar + 8) * XPAD + kb);
                    a[mf][2] = *(const uint32_t*)(A + ar * XPAD + kb + 8);
                    a[mf][3] = *(const uint32_t*)(A + (ar + 8) * XPAD + kb + 8);
                }
#pragma unroll
                for (int nf = 0; nf < 4; nf++) {
                    const int br = wn * 32 + nf * 8 + g;
                    b[nf][0] = *(const uint32_t*)(B + br * XPAD + kb);
                    b[nf][1] = *(const uint32_t*)(B + br * XPAD + kb + 8);
                }
#pragma unroll
                for (int mf = 0; mf < 4; mf++)
#pragma unroll
                    for (int nf = 0; nf < 4; nf++)
                        mma16816(acc[mf][nf], a[mf], b[nf]);
            }
        }

        // epilogue: add bias, write q fp32 / k,v fp16 into g_kv layout
        const float* bias = (m == 0) ? bq : ((m == 1) ? bk : bv);
        const int hoff = (m == 1) ? 0 : 2;   // k -> words 0..1, v -> words 2..3
#pragma unroll
        for (int mf = 0; mf < 4; mf++) {
            const int row = row0 + wm * 64 + mf * 16 + g;
#pragma unroll
            for (int nf = 0; nf < 4; nf++) {
                const int col = wn * 32 + nf * 8 + 2 * tig;
                const float bz0 = bias[col], bz1 = bias[col + 1];
                const float f0 = acc[mf][nf][0] + bz0, f1 = acc[mf][nf][1] + bz1;
                const float f2 = acc[mf][nf][2] + bz0, f3 = acc[mf][nf][3] + bz1;
                if (m == 0) {
                    if (row < n)     *(float2*)(g_q + (size_t)row * DM + col)       = make_float2(f0, f1);
                    if (row + 8 < n) *(float2*)(g_q + (size_t)(row + 8) * DM + col) = make_float2(f2, f3);
                } else {
                    const int word = hoff + ((col >> 1) & 1);
                    if (row < n)
                        ((__half2*)&g_kv[(size_t)row * 32 + (col >> 2)])[word] = __floats2half2_rn(f0, f1);
                    if (row + 8 < n)
                        ((__half2*)&g_kv[(size_t)(row + 8) * 32 + (col >> 2)])[word] = __floats2half2_rn(f2, f3);
                }
            }
        }
    }
}

// ---------------- CSR build ----------------
__global__ void zero_count_kernel(int n) {
    int i = blockIdx.x * blockDim.x + threadIdx.x;
    if (i < n) g_count[i] = 0;
}

__global__ void hist_kernel(const int* __restrict__ dst, int e) {
    for (int i = blockIdx.x * blockDim.x + threadIdx.x; i < e; i += gridDim.x * blockDim.x)
        atomicAdd(&g_count[dst[i]], 1);
}

__global__ __launch_bounds__(1024) void blockscan_kernel(int n) {
    __shared__ int s_wsum[32];
    const int tid = threadIdx.x;
    const int lane = tid & 31, wid = tid >> 5;
    const int i = blockIdx.x * 1024 + tid;
    int v = (i < n) ? g_count[i] : 0;
    int x = v;
#pragma unroll
    for (int o = 1; o < 32; o <<= 1) {
        int t = __shfl_up_sync(0xffffffffu, x, o);
        if (lane >= o) x += t;
    }
    if (lane == 31) s_wsum[wid] = x;
    __syncthreads();
    if (wid == 0) {
        int ws = s_wsum[lane];
#pragma unroll
        for (int o = 1; o < 32; o <<= 1) {
            int t = __shfl_up_sync(0xffffffffu, ws, o);
            if (lane >= o) ws += t;
        }
        s_wsum[lane] = ws;
    }
    __syncthreads();
    int excl = (wid ? s_wsum[wid - 1] : 0) + (x - v);
    if (i < n) g_rowptr[i] = excl;
    if (tid == 0) g_bsum[blockIdx.x] = s_wsum[31];
}

__global__ void bsumscan_kernel(int nb, int n) {
    const int lane = threadIdx.x;
    int carry = 0;
    for (int base = 0; base < nb; base += 32) {
        int idx = base + lane;
        int v = (idx < nb) ? g_bsum[idx] : 0;
        int x = v;
#pragma unroll
        for (int o = 1; o < 32; o <<= 1) {
            int t = __shfl_up_sync(0xffffffffu, x, o);
            if (lane >= o) x += t;
        }
        if (idx < nb) g_boff[idx] = carry + (x - v);
        carry += __shfl_sync(0xffffffffu, x, 31);
    }
    if (lane == 0) g_rowptr[n] = carry;
}

__global__ void addoff_kernel(int n) {
    int i = blockIdx.x * blockDim.x + threadIdx.x;
    if (i < n) {
        int r = g_rowptr[i] + g_boff[i >> 10];
        g_rowptr[i] = r;
        g_rowfill[i] = r;
    }
}

__global__ void scatter_kernel(const int* __restrict__ src, const int* __restrict__ dst, int e) {
    for (int i = blockIdx.x * blockDim.x + threadIdx.x; i < e; i += gridDim.x * blockDim.x) {
        int d = dst[i];
        int pos = atomicAdd(&g_rowfill[d], 1);
        g_elist[pos] = make_int2(i, src[i]);
    }
}

// ---------------- single-pass node kernel (unchanged R7 winner) ----------------
__global__ __launch_bounds__(256) void node_kernel(
    const float* __restrict__ pi,
    const float* __restrict__ view_w,
    float* __restrict__ out_states,   // [N, 128]
    float* __restrict__ out_attn,     // [E, 8] (unnormalized here)
    int n)
{
    const int nd = blockIdx.x * (blockDim.x >> 5) + (threadIdx.x >> 5);
    if (nd >= n) return;
    const int lane = threadIdx.x & 31;
    const unsigned FULL = 0xffffffffu;

    const int beg = g_rowptr[nd];
    const int end = g_rowptr[nd + 1];

    const float4 qv = *(const float4*)(g_q + (size_t)nd * DM + lane * 4);
    const int h = lane >> 2;
    const float* pip = pi + (size_t)nd * (HH * MV) + h * MV;
    const float pi0 = pip[0], pi1 = pip[1], pi2 = pip[2];

    float ssum = 0.f;
    float4 acc = make_float4(0.f, 0.f, 0.f, 0.f);

    int i = beg;
    for (; i + 1 < end; i += 2) {
        const int2 eA = g_elist[i];
        const int2 eB = g_elist[i + 1];

        const uint4 kvA = g_kv[(size_t)eA.y * 32 + lane];
        const uint4 kvB = g_kv[(size_t)eB.y * 32 + lane];

        const float* vwA = view_w + (size_t)eA.x * MV;
        const float* vwB = view_w + (size_t)eB.x * MV;
        const float mixA = pi0 * vwA[0] + pi1 * vwA[1] + pi2 * vwA[2];
        const float mixB = pi0 * vwB[0] + pi1 * vwB[1] + pi2 * vwB[2];

        const float2 kA01 = __half22float2(*(const __half2*)&kvA.x);
        const float2 kA23 = __half22float2(*(const __half2*)&kvA.y);
        const float2 kB01 = __half22float2(*(const __half2*)&kvB.x);
        const float2 kB23 = __half22float2(*(const __half2*)&kvB.y);

        float pA = qv.x * kA01.x + qv.y * kA01.y + qv.z * kA23.x + qv.w * kA23.y;
        float pB = qv.x * kB01.x + qv.y * kB01.y + qv.z * kB23.x + qv.w * kB23.y;
        pA += __shfl_xor_sync(FULL, pA, 1);
        pB += __shfl_xor_sync(FULL, pB, 1);
        pA += __shfl_xor_sync(FULL, pA, 2);
        pB += __shfl_xor_sync(FULL, pB, 2);

        const float wA = (mixA > 0.f) ? __expf(pA * 0.25f) * fmaxf(mixA, 1e-8f) : 0.f;
        const float wB = (mixB > 0.f) ? __expf(pB * 0.25f) * fmaxf(mixB, 1e-8f) : 0.f;
        ssum += wA + wB;

        const float wlA = __shfl_sync(FULL, wA, (lane & 7) * 4);
        const float wlB = __shfl_sync(FULL, wB, (lane & 7) * 4);
        if (lane < 8) {
            out_attn[(size_t)eA.x * HH + lane] = wlA;
            out_attn[(size_t)eB.x * HH + lane] = wlB;
        }

        const float2 vA01 = __half22float2(*(const __half2*)&kvA.z);
        const float2 vA23 = __half22float2(*(const __half2*)&kvA.w);
        const float2 vB01 = __half22float2(*(const __half2*)&kvB.z);
        const float2 vB23 = __half22float2(*(const __half2*)&kvB.w);
        acc.x += vA01.x * wA + vB01.x * wB;
        acc.y += vA01.y * wA + vB01.y * wB;
        acc.z += vA23.x * wA + vB23.x * wB;
        acc.w += vA23.y * wA + vB23.y * wB;
    }
    if (i < end) {
        const int2 eA = g_elist[i];
        const uint4 kvA = g_kv[(size_t)eA.y * 32 + lane];
        const float* vwA = view_w + (size_t)eA.x * MV;
        const float mixA = pi0 * vwA[0] + pi1 * vwA[1] + pi2 * vwA[2];
        const float2 kA01 = __half22float2(*(const __half2*)&kvA.x);
        const float2 kA23 = __half22float2(*(const __half2*)&kvA.y);
        float pA = qv.x * kA01.x + qv.y * kA01.y + qv.z * kA23.x + qv.w * kA23.y;
        pA += __shfl_xor_sync(FULL, pA, 1);
        pA += __shfl_xor_sync(FULL, pA, 2);
        const float wA = (mixA > 0.f) ? __expf(pA * 0.25f) * fmaxf(mixA, 1e-8f) : 0.f;
        ssum += wA;
        const float wlA = __shfl_sync(FULL, wA, (lane & 7) * 4);
        if (lane < 8) out_attn[(size_t)eA.x * HH + lane] = wlA;
        const float2 vA01 = __half22float2(*(const __half2*)&kvA.z);
        const float2 vA23 = __half22float2(*(const __half2*)&kvA.w);
        acc.x += vA01.x * wA;
        acc.y += vA01.y * wA;
        acc.z += vA23.x * wA;
        acc.w += vA23.y * wA;
    }

    const float inv = 1.f / fmaxf(ssum, 1e-8f);
    acc.x *= inv; acc.y *= inv; acc.z *= inv; acc.w *= inv;
    *(float4*)(out_states + (size_t)nd * DM + lane * 4) = acc;

    const float inv_h = __shfl_sync(FULL, inv, lane * 4);  // valid for lane<8
    if (lane < 8) g_inv[(size_t)nd * HH + lane] = inv_h;
}

// ---------------- edge-parallel attn normalization ----------------
__global__ __launch_bounds__(256) void normalize_kernel(
    const int* __restrict__ dst,
    float* __restrict__ out_attn,
    int e)
{
    const int i = blockIdx.x * blockDim.x + threadIdx.x;
    if (i >= e) return;
    const int d = dst[i];
    const float4 i0 = *(const float4*)(g_inv + (size_t)d * HH);
    const float4 i1 = *(const float4*)(g_inv + (size_t)d * HH + 4);
    float4 a0 = *(const float4*)(out_attn + (size_t)i * HH);
    float4 a1 = *(const float4*)(out_attn + (size_t)i * HH + 4);
    a0.x *= i0.x; a0.y *= i0.y; a0.z *= i0.z; a0.w *= i0.w;
    a1.x *= i1.x; a1.y *= i1.y; a1.z *= i1.z; a1.w *= i1.w;
    *(float4*)(out_attn + (size_t)i * HH)     = a0;
    *(float4*)(out_attn + (size_t)i * HH + 4) = a1;
}

// ---------------- launch ----------------
extern "C" void kernel_launch(void* const* d_in, const int* in_sizes, int n_in,
                              void* d_out, int out_size)
{
    const float* x   = (const float*)d_in[0];
    const float* pi  = (const float*)d_in[1];
    const float* vw  = (const float*)d_in[2];
    const float* Wq  = (const float*)d_in[3];
    const float* bq  = (const float*)d_in[4];
    const float* Wk  = (const float*)d_in[5];
    const float* bk  = (const float*)d_in[6];
    const float* Wv  = (const float*)d_in[7];
    const float* bv  = (const float*)d_in[8];
    const int*   src = (const int*)d_in[9];
    const int*   dst = (const int*)d_in[10];

    const int n = in_sizes[0] / DM;    // nodes
    const int e = in_sizes[10];        // edges

    float* out  = (float*)d_out;
    float* attn = out + (size_t)n * DM;

    int gb = (e + 255) / 256;
    if (gb > 4096) gb = 4096;

    const int nb = (n + 1023) / 1024;  // scan blocks (<=128)

    cudaFuncSetAttribute(qkv_mma_kernel, cudaFuncAttributeMaxDynamicSharedMemorySize, QKV_SMEM_BYTES);

    // W prep + tensor-core QKV projection
    prep_w_kernel<<<(6 * 16384 + 255) / 256, 256>>>(Wq, Wk, Wv);
    qkv_mma_kernel<<<(n + 127) / 128, 256, QKV_SMEM_BYTES>>>(x, bq, bk, bv, n);

    // CSR by dst (parallel 3-phase scan)
    zero_count_kernel<<<(n + 255) / 256, 256>>>(n);
    hist_kernel<<<gb, 256>>>(dst, e);
    blockscan_kernel<<<nb, 1024>>>(n);
    bsumscan_kernel<<<1, 32>>>(nb, n);
    addoff_kernel<<<(n + 255) / 256, 256>>>(n);
    scatter_kernel<<<gb, 256>>>(src, dst, e);

    // single-pass fused scores + softmax + aggregation
    node_kernel<<<(n + 7) / 8, 256>>>(pi, vw, out, attn, n);

    // edge-parallel attn normalization
    normalize_kernel<<<(e + 255) / 256, 256>>>(dst, attn, e);
}